// round 15
// baseline (speedup 1.0000x reference)
#include <cuda_runtime.h>
#include <cuda_bf16.h>
#include <cuda_fp16.h>
#include <math.h>
#include <stdint.h>

// ---------------- problem constants ----------------
#define NB     1024
#define NV     6890
#define NJ     24
#define NPOSE  207
#define TROWS  224
#define M2     672      // 3 * TROWS
#define MPAD   768
#define N2     576      // jk pairs
#define NQ     1728     // 3 * 576
#define KPAD   6912
#define GDIM   224

#define ASCALE 1024.f
#define INVSC  (1.f/1024.f)

// big GEMM tiling (fp16, 2-pass)
#define BM 128
#define BN 64
#define BK 32
#define AHSZ (BM*BK*2)          // 8192 B per A half
#define BHSZ (BN*BK*2)          // 4096 B (single fp16 B)
#define MSTG (2*AHSZ + BHSZ)    // 20480 B per stage
#define MNST 3
#define MSMEM (MNST*MSTG)       // 61440 B  (>= 128*65*4 = 33280 for reduce reuse)
#define ZSPL 8                  // 432 CTAs = single wave @3/SM
#define KIT  27                 // 864/32 k-blocks per CTA
#define NTILES 54               // 9 x 6 output tiles

// small GEMM tiling: 64x64 tiles, 128 threads, 432 CTAs (bf16, 3-pass)
#define S2ASZ (64*BK*2)
#define S2STG (2*S2ASZ)
#define S2SMEM (4*S2STG)
#define G3ITER 21

#define FEAT_BLOCKS (NB/8)
#define JB_BLOCKS 4

__constant__ int c_parents[24] = {-1,0,0,0,1,2,3,4,5,6,7,8,9,9,9,12,13,14,16,17,18,19,20,21};

// ---------------- device scratch ----------------
__device__ __align__(16) __half d_Ah[MPAD * KPAD];
__device__ __align__(16) __half d_Al[MPAD * KPAD];
__device__ __align__(16) __half d_B [N2 * KPAD];
__device__ __align__(16) float d_Jrt[NJ * KPAD];
__device__ __align__(16) float d_wt [NJ * KPAD];
__device__ __align__(16) float d_Cpart[ZSPL * MPAD * N2];
__device__ __align__(16) float d_C2row[N2];              // only row 218 of C2 needed
__device__ __align__(16) __nv_bfloat16 d_Bth[NQ * GDIM];
__device__ __align__(16) __nv_bfloat16 d_Btl[NQ * GDIM];
__device__ float d_Jb[3 * 11 * NJ];
__device__ __align__(16) __nv_bfloat16 d_gh[NB * GDIM];
__device__ __align__(16) __nv_bfloat16 d_gl[NB * GDIM];
__device__ float d_Rs[NB * NJ * 9];
__device__ float d_Qv[NB * NQ];
__device__ unsigned int d_cnt[NTILES];                   // self-resetting arrival counters

// ---------------- helpers ----------------
__device__ __forceinline__ uint32_t smem_u32(const void* p) {
    uint32_t r;
    asm("{ .reg .u64 t; cvta.to.shared.u64 t, %1; cvt.u32.u64 %0, t; }" : "=r"(r) : "l"(p));
    return r;
}
__device__ __forceinline__ void cp_async16(uint32_t saddr, const void* gaddr) {
    asm volatile("cp.async.cg.shared.global [%0], [%1], 16;" :: "r"(saddr), "l"(gaddr) : "memory");
}
__device__ __forceinline__ void cp_commit() {
    asm volatile("cp.async.commit_group;" ::: "memory");
}
__device__ __forceinline__ void ldsm_x4(uint32_t& r0, uint32_t& r1, uint32_t& r2, uint32_t& r3,
                                        uint32_t addr) {
    asm volatile("ldmatrix.sync.aligned.m8n8.x4.shared.b16 {%0,%1,%2,%3}, [%4];"
                 : "=r"(r0), "=r"(r1), "=r"(r2), "=r"(r3) : "r"(addr));
}
// bf16 mma (for gemm3m)
__device__ __forceinline__ void mma16816(float& d0, float& d1, float& d2, float& d3,
                                         uint32_t a0, uint32_t a1, uint32_t a2, uint32_t a3,
                                         uint32_t b0, uint32_t b1) {
    asm volatile("mma.sync.aligned.m16n8k16.row.col.f32.bf16.bf16.f32 "
                 "{%0,%1,%2,%3}, {%4,%5,%6,%7}, {%8,%9}, {%0,%1,%2,%3};"
                 : "+f"(d0), "+f"(d1), "+f"(d2), "+f"(d3)
                 : "r"(a0), "r"(a1), "r"(a2), "r"(a3), "r"(b0), "r"(b1));
}
// fp16 mma (for big GEMM)
__device__ __forceinline__ void mma16816h(float& d0, float& d1, float& d2, float& d3,
                                          uint32_t a0, uint32_t a1, uint32_t a2, uint32_t a3,
                                          uint32_t b0, uint32_t b1) {
    asm volatile("mma.sync.aligned.m16n8k16.row.col.f32.f16.f16.f32 "
                 "{%0,%1,%2,%3}, {%4,%5,%6,%7}, {%8,%9}, {%0,%1,%2,%3};"
                 : "+f"(d0), "+f"(d1), "+f"(d2), "+f"(d3)
                 : "r"(a0), "r"(a1), "r"(a2), "r"(a3), "r"(b0), "r"(b1));
}
// swizzled byte offset in a [rows][32 x 16-bit] tile: row r, 16B chunk c in 0..3
__device__ __forceinline__ uint32_t swz32(int r, int c) {
    return (uint32_t)(r * 64 + ((c ^ ((r >> 1) & 3)) << 4));
}

// pack 4 floats into bf16 hi/lo 8-byte words
union PKB { __nv_bfloat16 b[4]; uint2 u; };
__device__ __forceinline__ void pack_hl(const float* v, uint2& hu, uint2& lu) {
    PKB H, L;
#pragma unroll
    for (int q = 0; q < 4; ++q) {
        __nv_bfloat16 h = __float2bfloat16(v[q]);
        H.b[q] = h;
        L.b[q] = __float2bfloat16(v[q] - __bfloat162float(h));
    }
    hu = H.u; lu = L.u;
}
// pack 4 floats (pre-scaled) into fp16 hi/lo 8-byte words
union PKH { __half b[4]; uint2 u; };
__device__ __forceinline__ void pack_hl_h(const float* v, uint2& hu, uint2& lu) {
    PKH H, L;
#pragma unroll
    for (int q = 0; q < 4; ++q) {
        float s = v[q] * ASCALE;
        __half h = __float2half_rn(s);
        H.b[q] = h;
        L.b[q] = __float2half_rn(s - __half2float(h));
    }
    hu = H.u; lu = L.u;
}
__device__ __forceinline__ uint2 pack_h(const float* v) {
    PKH P;
#pragma unroll
    for (int q = 0; q < 4; ++q) P.b[q] = __float2half_rn(v[q]);
    return P.u;
}

// ---------------- prep: gather A (fp16 hi/lo, scaled) + transpose Jr/w ----------
__global__ void k_prep(const float* __restrict__ posedirs,
                       const float* __restrict__ shapedirs,
                       const float* __restrict__ vtempl,
                       const float* __restrict__ Jr, const float* __restrict__ w,
                       __half* __restrict__ Ah, __half* __restrict__ Al,
                       float* __restrict__ Jrt, float* __restrict__ wt)
{
    const int idx = blockIdx.x * 256 + threadIdx.x;
    const int y = blockIdx.y;
    const int v = idx * 4;
    if (v >= KPAD) return;

    if (y < TROWS) {
        const int t = y;
        float c0[4] = {0,0,0,0}, c1[4] = {0,0,0,0}, c2[4] = {0,0,0,0};
        const float* src = nullptr;
        if (t < NPOSE)           src = posedirs + (size_t)t * (NV*3);
        else if (t < NPOSE + 10) src = shapedirs + (size_t)(t-NPOSE) * (NV*3);
        else if (t == 217)       src = vtempl;

        if (src) {
            if (v + 3 < NV) {
                const float2* s2 = (const float2*)(src + (size_t)v*3);
                float2 f0 = s2[0], f1 = s2[1], f2 = s2[2];
                float2 f3 = s2[3], f4 = s2[4], f5 = s2[5];
                c0[0]=f0.x; c1[0]=f0.y; c2[0]=f1.x;
                c0[1]=f1.y; c1[1]=f2.x; c2[1]=f2.y;
                c0[2]=f3.x; c1[2]=f3.y; c2[2]=f4.x;
                c0[3]=f4.y; c1[3]=f5.x; c2[3]=f5.y;
            } else {
                for (int q = 0; q < 4 && v + q < NV; ++q) {
                    c0[q] = src[(size_t)(v+q)*3 + 0];
                    c1[q] = src[(size_t)(v+q)*3 + 1];
                    c2[q] = src[(size_t)(v+q)*3 + 2];
                }
            }
        } else if (t == 218) {
#pragma unroll
            for (int q = 0; q < 4; ++q) c0[q] = (v + q < NV) ? 1.f : 0.f;
        } else {
            return;   // pad rows stay zero (zero-initialized globals)
        }

        const float* ch[3] = {c0, c1, c2};
#pragma unroll
        for (int c = 0; c < 3; ++c) {
            uint2 hu, lu;
            pack_hl_h(ch[c], hu, lu);
            size_t o = (size_t)(c*TROWS + t) * KPAD + v;
            *(uint2*)(Ah + o) = hu;
            *(uint2*)(Al + o) = lu;
        }
        return;
    }

    const int j = y - TROWS;
    float a[4] = {0,0,0,0}, b[4] = {0,0,0,0};
#pragma unroll
    for (int q = 0; q < 4; ++q) {
        if (v + q < NV) {
            a[q] = Jr[(size_t)(v+q)*24 + j];
            b[q] = w [(size_t)(v+q)*24 + j];
        }
    }
    *(float4*)(Jrt + (size_t)j * KPAD + v) = make_float4(a[0], a[1], a[2], a[3]);
    *(float4*)(wt  + (size_t)j * KPAD + v) = make_float4(b[0], b[1], b[2], b[3]);
}

// ---------------- B[jk][v] = Jr[v,j]*w[v,k] -> single fp16 ----------------
__global__ void k_prepB(const float* __restrict__ Jrt, const float* __restrict__ wt,
                        __half* __restrict__ B)
{
    const int idx = blockIdx.x * 256 + threadIdx.x;
    const int v = idx * 4;
    if (v >= KPAD) return;
    const int jk = blockIdx.y;
    const int j = jk / 24, k = jk - j * 24;

    float4 a = *(const float4*)(Jrt + (size_t)j * KPAD + v);
    float4 b = *(const float4*)(wt  + (size_t)k * KPAD + v);
    float p[4] = {a.x*b.x, a.y*b.y, a.z*b.z, a.w*b.w};
    *(uint2*)(B + (size_t)jk * KPAD + v) = pack_h(p);
}

// ---------------- big projection GEMM (fp16, 2-pass) + fused reduce tail -------
__global__ __launch_bounds__(256, 3) void k_mma(const __half* __restrict__ Ah,
                                                const __half* __restrict__ Al,
                                                const __half* __restrict__ B,
                                                float* __restrict__ Cpart,
                                                float* __restrict__ C2row,
                                                __nv_bfloat16* __restrict__ Bth,
                                                __nv_bfloat16* __restrict__ Btl,
                                                unsigned int* __restrict__ cnt)
{
    extern __shared__ char sm[];
    __shared__ int s_last;
    const uint32_t sbase = smem_u32(sm);
    const int tid = threadIdx.x;
    const int lane = tid & 31, wid = tid >> 5;
    const int n0 = blockIdx.x * BN;
    const int m0 = blockIdx.y * BM;
    const int kbase = blockIdx.z * (KIT * BK);

    const int wm = wid & 3;
    const int wn = wid >> 2;

    const int lr = tid >> 2, lc = tid & 3;

    auto load_stage = [&](int t) {
        const uint32_t s0 = sbase + (uint32_t)(t % MNST) * MSTG;
        const uint32_t sAh = s0;
        const uint32_t sAl = s0 + AHSZ;
        const uint32_t sB  = s0 + 2*AHSZ;
        const int kk = kbase + t * BK;
        cp_async16(sAh + swz32(lr,      lc), Ah + (size_t)(m0 + lr)      * KPAD + kk + lc*8);
        cp_async16(sAh + swz32(lr + 64, lc), Ah + (size_t)(m0 + lr + 64) * KPAD + kk + lc*8);
        cp_async16(sAl + swz32(lr,      lc), Al + (size_t)(m0 + lr)      * KPAD + kk + lc*8);
        cp_async16(sAl + swz32(lr + 64, lc), Al + (size_t)(m0 + lr + 64) * KPAD + kk + lc*8);
        cp_async16(sB  + swz32(lr, lc),      B  + (size_t)(n0 + lr)      * KPAD + kk + lc*8);
        cp_commit();
    };

    float acc[2][4][4] = {};

    load_stage(0);
    load_stage(1);

    for (int t = 0; t < KIT; ++t) {
        asm volatile("cp.async.wait_group 1;" ::: "memory");
        __syncthreads();
        if (t + 2 < KIT) load_stage(t + 2);

        const uint32_t s0  = sbase + (uint32_t)(t % MNST) * MSTG;
        const uint32_t sAh = s0;
        const uint32_t sAl = s0 + AHSZ;
        const uint32_t sB  = s0 + 2*AHSZ;

#pragma unroll
        for (int ks = 0; ks < 2; ++ks) {
            uint32_t bb[4][2];
#pragma unroll
            for (int j2 = 0; j2 < 2; j2++) {
                int n = wn*32 + j2*16 + (lane & 7) + ((lane >> 4) << 3);
                int c = ks*2 + ((lane >> 3) & 1);
                uint32_t q0, q1, q2, q3;
                ldsm_x4(q0, q1, q2, q3, sB + swz32(n, c));
                bb[j2*2+0][0] = q0; bb[j2*2+0][1] = q1;
                bb[j2*2+1][0] = q2; bb[j2*2+1][1] = q3;
            }
            {
                uint32_t ah[2][4];
#pragma unroll
                for (int i = 0; i < 2; i++) {
                    int r = wm*32 + i*16 + (lane & 15);
                    int c = ks*2 + (lane >> 4);
                    ldsm_x4(ah[i][0], ah[i][1], ah[i][2], ah[i][3], sAh + swz32(r, c));
                }
#pragma unroll
                for (int i = 0; i < 2; i++)
#pragma unroll
                    for (int j = 0; j < 4; j++)
                        mma16816h(acc[i][j][0], acc[i][j][1], acc[i][j][2], acc[i][j][3],
                                  ah[i][0], ah[i][1], ah[i][2], ah[i][3], bb[j][0], bb[j][1]);
            }
            {
                uint32_t al[2][4];
#pragma unroll
                for (int i = 0; i < 2; i++) {
                    int r = wm*32 + i*16 + (lane & 15);
                    int c = ks*2 + (lane >> 4);
                    ldsm_x4(al[i][0], al[i][1], al[i][2], al[i][3], sAl + swz32(r, c));
                }
#pragma unroll
                for (int i = 0; i < 2; i++)
#pragma unroll
                    for (int j = 0; j < 4; j++)
                        mma16816h(acc[i][j][0], acc[i][j][1], acc[i][j][2], acc[i][j][3],
                                  al[i][0], al[i][1], al[i][2], al[i][3], bb[j][0], bb[j][1]);
            }
        }
    }

    // ---- split-K partial store ----
    float* cp = Cpart + (size_t)blockIdx.z * ((size_t)MPAD * N2);
#pragma unroll
    for (int i = 0; i < 2; i++) {
        int row = m0 + wm*32 + i*16 + (lane >> 2);
        if (row < M2) {
#pragma unroll
            for (int j = 0; j < 4; j++) {
                int col = n0 + wn*32 + j*8 + (lane & 3)*2;
                *(float2*)(cp + (size_t)row * N2 + col)       = make_float2(acc[i][j][0], acc[i][j][1]);
                *(float2*)(cp + (size_t)(row + 8) * N2 + col) = make_float2(acc[i][j][2], acc[i][j][3]);
            }
        }
    }

    // ---- fence + arrival counter (threadFenceReduction pattern) ----
    __threadfence();
    __syncthreads();
    if (tid == 0) {
        unsigned int old = atomicInc(&cnt[blockIdx.y * 9 + blockIdx.x], ZSPL - 1);
        s_last = (old == ZSPL - 1);
    }
    __syncthreads();
    if (!s_last) return;

    // ---- last CTA: reduce 8 L2-hot slices, unscale, transpose to bf16 hi/lo ----
    float* sred = (float*)sm;                 // [128][65] floats = 33280 B (pipeline smem reused)
#pragma unroll
    for (int s = 0; s < 8; ++s) {
        int slot = tid + s * 256;             // 0..2047
        int m = slot >> 4;                    // 0..127
        int n4 = (slot & 15) * 4;
        int gm = m0 + m;
        float4 sum = make_float4(0.f, 0.f, 0.f, 0.f);
        if (gm < M2) {
#pragma unroll
            for (int p = 0; p < ZSPL; ++p) {
                float4 vv = *(const float4*)(Cpart + (size_t)p * (MPAD*N2)
                                             + (size_t)gm * N2 + n0 + n4);
                sum.x += vv.x; sum.y += vv.y; sum.z += vv.z; sum.w += vv.w;
            }
            sum.x *= INVSC; sum.y *= INVSC; sum.z *= INVSC; sum.w *= INVSC;
            if (gm == 218)
                *(float4*)(C2row + n0 + n4) = sum;
        }
        sred[m*65 + n4 + 0] = sum.x;
        sred[m*65 + n4 + 1] = sum.y;
        sred[m*65 + n4 + 2] = sum.z;
        sred[m*65 + n4 + 3] = sum.w;
    }
    __syncthreads();

    const int n_loc = tid >> 2;               // 0..63
    const int tq = tid & 3;
#pragma unroll
    for (int s = 0; s < 8; ++s) {
        int chunk = tq + s * 4;                // 0..31, 4 rows each
        int gm = m0 + chunk * 4;
        if (gm >= M2) continue;
        int c = gm / TROWS;                    // chunks of 4 never straddle (224 % 4 == 0)
        int t0r = gm - c * TROWS;
        float v[4];
#pragma unroll
        for (int q = 0; q < 4; ++q) v[q] = sred[(chunk*4 + q)*65 + n_loc];
        uint2 hu, lu;
        pack_hl(v, hu, lu);
        size_t o = (size_t)(c*N2 + n0 + n_loc) * GDIM + t0r;
        *(uint2*)(Bth + o) = hu;
        *(uint2*)(Btl + o) = lu;
    }
}

// ---------------- features (Rodrigues -> bf16 hi/lo) + rest-joint basis --------
__global__ void k_mid(const float* __restrict__ Cpart,
                      const float* __restrict__ beta,
                      const float* __restrict__ theta,
                      __nv_bfloat16* __restrict__ gh, __nv_bfloat16* __restrict__ gl,
                      float* __restrict__ Rs, float* __restrict__ Jb)
{
    const int bid = blockIdx.x;
    const int tid = threadIdx.x;

    if (bid < FEAT_BLOCKS) {
        const int b = bid * 8 + (tid >> 5);
        const int lane = tid & 31;
        auto wr = [&](int idx, float v) {
            __nv_bfloat16 h = __float2bfloat16(v);
            __nv_bfloat16 l = __float2bfloat16(v - __bfloat162float(h));
            gh[(size_t)b*GDIM + idx] = h;
            gl[(size_t)b*GDIM + idx] = l;
        };
        if (lane < 24) {
            int k = lane;
            float t0 = theta[b*72 + k*3 + 0];
            float t1 = theta[b*72 + k*3 + 1];
            float t2 = theta[b*72 + k*3 + 2];
            float a0 = t0 + 1e-8f, a1 = t1 + 1e-8f, a2 = t2 + 1e-8f;
            float angle = sqrtf(a0*a0 + a1*a1 + a2*a2);
            float inv = 1.f / angle;
            float n0 = t0*inv, n1 = t1*inv, n2 = t2*inv;
            float half = 0.5f * angle;
            float w = cosf(half), s = sinf(half);
            float x = s*n0, y = s*n1, z = s*n2;
            float qn = rsqrtf(w*w + x*x + y*y + z*z);
            w *= qn; x *= qn; y *= qn; z *= qn;
            float rot[9];
            rot[0] = w*w + x*x - y*y - z*z;
            rot[1] = 2.f*(x*y - w*z);
            rot[2] = 2.f*(x*z + w*y);
            rot[3] = 2.f*(x*y + w*z);
            rot[4] = w*w - x*x + y*y - z*z;
            rot[5] = 2.f*(y*z - w*x);
            rot[6] = 2.f*(x*z - w*y);
            rot[7] = 2.f*(y*z + w*x);
            rot[8] = w*w - x*x - y*y + z*z;
            float* rs = Rs + (size_t)(b*24 + k) * 9;
#pragma unroll
            for (int e = 0; e < 9; e++) rs[e] = rot[e];
            if (k > 0) {
#pragma unroll
                for (int e = 0; e < 9; e++)
                    wr((k-1)*9 + e, rot[e] - ((e == 0 || e == 4 || e == 8) ? 1.f : 0.f));
            }
        }
        if (lane < 10)       wr(207 + lane, beta[b*10 + lane]);
        else if (lane == 10) wr(217, 1.f);
        else if (lane < 17)  wr(207 + lane, 0.f);
        return;
    }

    // rest-joint basis (reads Cpart directly, with unscale)
    {
        const int idx = (bid - FEAT_BLOCKS) * 256 + tid;
        if (idx >= 3*11*NJ) return;
        int c = idx / (11*NJ);
        int r = idx - c * (11*NJ);
        int i = r / NJ;
        int j = r - i * NJ;
        const size_t rowoff = (size_t)(c*TROWS + 207 + i) * N2 + j*24;
        float s = 0.f;
#pragma unroll
        for (int p = 0; p < ZSPL; ++p) {
            const float* row = Cpart + (size_t)p * (MPAD*N2) + rowoff;
#pragma unroll
            for (int k = 0; k < 24; k++) s += row[k];
        }
        Jb[idx] = s * INVSC;
    }
}

// ---------------- per-batch GEMM Qv = g @ C2t^T (bf16 mma, 3-pass) --------------
__global__ __launch_bounds__(128) void k_gemm3m(const __nv_bfloat16* __restrict__ gh,
                                                const __nv_bfloat16* __restrict__ gl,
                                                const __nv_bfloat16* __restrict__ Bth,
                                                const __nv_bfloat16* __restrict__ Btl,
                                                float* __restrict__ Qv)
{
    extern __shared__ char sm[];
    const uint32_t sbase = smem_u32(sm);
    const int tid = threadIdx.x;
    const int lane = tid & 31, wid = tid >> 5;
    const int n0 = blockIdx.x * 64;
    const int m0 = blockIdx.y * 64;

    const int lr0 = tid >> 2, lc0 = tid & 3;
    const int lr1 = lr0 + 32;

    auto load_stage = [&](int t) {
        const int seg = t / 7;
        const int kk = (t - seg*7) * BK;
        const __nv_bfloat16* Aptr = (seg == 2) ? gl : gh;
        const __nv_bfloat16* Bptr = (seg == 1) ? Btl : Bth;
        const uint32_t sa = sbase + (uint32_t)(t & 3) * S2STG;
        const uint32_t sb = sa + S2ASZ;
        cp_async16(sa + swz32(lr0, lc0), Aptr + (size_t)(m0 + lr0) * GDIM + kk + lc0*8);
        cp_async16(sa + swz32(lr1, lc0), Aptr + (size_t)(m0 + lr1) * GDIM + kk + lc0*8);
        cp_async16(sb + swz32(lr0, lc0), Bptr + (size_t)(n0 + lr0) * GDIM + kk + lc0*8);
        cp_async16(sb + swz32(lr1, lc0), Bptr + (size_t)(n0 + lr1) * GDIM + kk + lc0*8);
        cp_commit();
    };

    float acc[8][4] = {};

    load_stage(0);
    load_stage(1);
    load_stage(2);

    for (int t = 0; t < G3ITER; ++t) {
        asm volatile("cp.async.wait_group 2;" ::: "memory");
        __syncthreads();
        if (t + 3 < G3ITER) load_stage(t + 3);

        const uint32_t sa = sbase + (uint32_t)(t & 3) * S2STG;
        const uint32_t sb = sa + S2ASZ;
#pragma unroll
        for (int ks = 0; ks < 2; ++ks) {
            uint32_t a[4];
            {
                int r = wid*16 + (lane & 15);
                int c = ks*2 + (lane >> 4);
                ldsm_x4(a[0], a[1], a[2], a[3], sa + swz32(r, c));
            }
            uint32_t bfr[8][2];
#pragma unroll
            for (int j2 = 0; j2 < 4; j2++) {
                int n = j2*16 + (lane & 7) + ((lane >> 4) << 3);
                int c = ks*2 + ((lane >> 3) & 1);
                uint32_t q0, q1, q2, q3;
                ldsm_x4(q0, q1, q2, q3, sb + swz32(n, c));
                bfr[j2*2+0][0] = q0; bfr[j2*2+0][1] = q1;
                bfr[j2*2+1][0] = q2; bfr[j2*2+1][1] = q3;
            }
#pragma unroll
            for (int j = 0; j < 8; j++)
                mma16816(acc[j][0], acc[j][1], acc[j][2], acc[j][3],
                         a[0], a[1], a[2], a[3], bfr[j][0], bfr[j][1]);
        }
    }

    {
        int row = m0 + wid*16 + (lane >> 2);
#pragma unroll
        for (int j = 0; j < 8; j++) {
            int col = n0 + j*8 + (lane & 3)*2;
            *(float2*)(Qv + (size_t)row * NQ + col)       = make_float2(acc[j][0], acc[j][1]);
            *(float2*)(Qv + (size_t)(row + 8) * NQ + col) = make_float2(acc[j][2], acc[j][3]);
        }
    }
}

// ---------------- kinematic chain + combine ----------------
__global__ __launch_bounds__(128) void k_final(const float* __restrict__ beta,
                                               const float* __restrict__ Rs,
                                               const float* __restrict__ Jb,
                                               const float* __restrict__ C2row,
                                               const float* __restrict__ Qv,
                                               float* __restrict__ out)
{
    __shared__ float sR[216];
    __shared__ float sJ[72];
    __shared__ float sG[288];
    __shared__ float sAt[72];
    __shared__ float sBeta[10];
    const int b = blockIdx.x;
    const int tid = threadIdx.x;

    for (int i = tid; i < 216; i += 128) sR[i] = Rs[(size_t)b*216 + i];
    if (tid < 10) sBeta[tid] = beta[b*10 + tid];
    __syncthreads();

    if (tid < 72) {
        int j = tid / 3, c = tid - j*3;
        float v = Jb[(c*11 + 10)*NJ + j];
#pragma unroll
        for (int i = 0; i < 10; i++) v = fmaf(sBeta[i], Jb[(c*11 + i)*NJ + j], v);
        sJ[j*3 + c] = v;
    }
    __syncthreads();

    if (tid < 12) {
        int r = tid >> 2, cc = tid & 3;
        sG[tid] = (cc < 3) ? sR[r*3 + cc] : sJ[r];
        __syncwarp(0x0fff);
        for (int i = 1; i < 24; i++) {
            int p = c_parents[i];
            float v;
            if (cc < 3) {
                v = sG[p*12 + r*4 + 0] * sR[i*9 + 0 + cc]
                  + sG[p*12 + r*4 + 1] * sR[i*9 + 3 + cc]
                  + sG[p*12 + r*4 + 2] * sR[i*9 + 6 + cc];
            } else {
                float tx = sJ[i*3+0] - sJ[p*3+0];
                float ty = sJ[i*3+1] - sJ[p*3+1];
                float tz = sJ[i*3+2] - sJ[p*3+2];
                v = sG[p*12 + r*4 + 0] * tx
                  + sG[p*12 + r*4 + 1] * ty
                  + sG[p*12 + r*4 + 2] * tz
                  + sG[p*12 + r*4 + 3];
            }
            sG[i*12 + r*4 + cc] = v;
            __syncwarp(0x0fff);
        }
    }
    __syncthreads();

    if (tid < 72) {
        int k = tid / 3, c = tid - k*3;
        sAt[k*3 + c] = sG[k*12 + c*4 + 3]
                     - (sG[k*12 + c*4 + 0] * sJ[k*3 + 0]
                      + sG[k*12 + c*4 + 1] * sJ[k*3 + 1]
                      + sG[k*12 + c*4 + 2] * sJ[k*3 + 2]);
    }
    __syncthreads();

    if (tid < 72) {
        int j = tid / 3, c = tid - j*3;
        const float* qb = Qv + (size_t)b * NQ;
        float acc = 0.f;
#pragma unroll
        for (int k = 0; k < 24; k++) {
            int jk = j*24 + k;
            acc = fmaf(sG[k*12 + c*4 + 0], qb[jk],        acc);
            acc = fmaf(sG[k*12 + c*4 + 1], qb[576 + jk],  acc);
            acc = fmaf(sG[k*12 + c*4 + 2], qb[1152 + jk], acc);
            acc = fmaf(sAt[k*3 + c],       C2row[jk],     acc);
        }
        out[b*72 + j*3 + c] = acc;
    }
}

// ---------------- launcher ----------------
extern "C" void kernel_launch(void* const* d_in, const int* in_sizes, int n_in,
                              void* d_out, int out_size)
{
    const float* beta      = (const float*)d_in[0];
    const float* theta     = (const float*)d_in[1];
    const float* vtempl    = (const float*)d_in[2];
    const float* shapedirs = (const float*)d_in[3];
    const float* posedirs  = (const float*)d_in[4];
    const float* Jr        = (const float*)d_in[5];
    const float* wts       = (const float*)d_in[6];
    float* out = (float*)d_out;

    __half *Ah, *Al, *B;
    __nv_bfloat16 *Bth, *Btl, *gh, *gl;
    float *Jrt, *wt, *Cpart, *C2row, *Jb, *Rs, *Qv;
    unsigned int* cnt;
    cudaGetSymbolAddress((void**)&Ah, d_Ah);
    cudaGetSymbolAddress((void**)&Al, d_Al);
    cudaGetSymbolAddress((void**)&B,  d_B);
    cudaGetSymbolAddress((void**)&Bth, d_Bth);
    cudaGetSymbolAddress((void**)&Btl, d_Btl);
    cudaGetSymbolAddress((void**)&gh, d_gh);
    cudaGetSymbolAddress((void**)&gl, d_gl);
    cudaGetSymbolAddress((void**)&Jrt, d_Jrt);
    cudaGetSymbolAddress((void**)&wt, d_wt);
    cudaGetSymbolAddress((void**)&Cpart, d_Cpart);
    cudaGetSymbolAddress((void**)&C2row, d_C2row);
    cudaGetSymbolAddress((void**)&Jb, d_Jb);
    cudaGetSymbolAddress((void**)&Rs, d_Rs);
    cudaGetSymbolAddress((void**)&Qv, d_Qv);
    cudaGetSymbolAddress((void**)&cnt, d_cnt);

    cudaFuncSetAttribute(k_mma,    cudaFuncAttributeMaxDynamicSharedMemorySize, MSMEM);
    cudaFuncSetAttribute(k_gemm3m, cudaFuncAttributeMaxDynamicSharedMemorySize, S2SMEM);

    k_prep<<<dim3(7, TROWS + NJ), 256>>>(posedirs, shapedirs, vtempl, Jr, wts,
                                         Ah, Al, Jrt, wt);
    k_prepB<<<dim3(7, N2), 256>>>(Jrt, wt, B);
    k_mma<<<dim3(N2/BN, MPAD/BM, ZSPL), 256, MSMEM>>>(Ah, Al, B, Cpart,
                                                      C2row, Bth, Btl, cnt);
    k_mid<<<FEAT_BLOCKS + JB_BLOCKS, 256>>>(Cpart, beta, theta, gh, gl, Rs, Jb);
    k_gemm3m<<<dim3(NQ/64, NB/64), 128, S2SMEM>>>(gh, gl, Bth, Btl, Qv);
    k_final<<<NB, 128>>>(beta, Rs, Jb, C2row, Qv, out);
}

// round 16
// speedup vs baseline: 1.3340x; 1.3340x over previous
#include <cuda_runtime.h>
#include <cuda_bf16.h>
#include <cuda_fp16.h>
#include <math.h>
#include <stdint.h>

// ---------------- problem constants ----------------
#define NB     1024
#define NV     6890
#define NJ     24
#define NPOSE  207
#define TROWS  224
#define M2     672      // 3 * TROWS
#define MPAD   768
#define N2     576      // jk pairs
#define NQ     1728     // 3 * 576
#define KPAD   6912
#define GDIM   224

#define ASCALE 1024.f
#define INVSC  (1.f/1024.f)

// big GEMM tiling (fp16, 2-pass)
#define BM 128
#define BN 64
#define BK 32
#define AHSZ (BM*BK*2)          // 8192 B per A half
#define BHSZ (BN*BK*2)          // 4096 B (single fp16 B)
#define MSTG (2*AHSZ + BHSZ)    // 20480 B per stage
#define MNST 3
#define MSMEM (MNST*MSTG)       // 61440 B
#define ZSPL 8                  // 432 CTAs = single wave @3/SM
#define KIT  27                 // 864/32 k-blocks per CTA

// small GEMM tiling: 64x64 tiles, 128 threads, 432 CTAs (bf16, 3-pass)
#define S2ASZ (64*BK*2)
#define S2STG (2*S2ASZ)
#define S2SMEM (4*S2STG)
#define G3ITER 21

#define TR2_BLOCKS 378          // 18 * 21
#define FEAT_BLOCKS (NB/8)      // 128
#define JB_OUT (3*11*NJ)        // 792 outputs
#define JB_BLOCKS 99            // 792 / 8 warps

__constant__ int c_parents[24] = {-1,0,0,0,1,2,3,4,5,6,7,8,9,9,9,12,13,14,16,17,18,19,20,21};

// ---------------- device scratch ----------------
__device__ __align__(16) __half d_Ah[MPAD * KPAD];
__device__ __align__(16) __half d_Al[MPAD * KPAD];
__device__ __align__(16) __half d_B [N2 * KPAD];
__device__ __align__(16) float d_Jrt[NJ * KPAD];
__device__ __align__(16) float d_wt [NJ * KPAD];
__device__ __align__(16) float d_Cpart[ZSPL * MPAD * N2];
__device__ __align__(16) float d_C2[MPAD * N2];
__device__ __align__(16) __nv_bfloat16 d_Bth[NQ * GDIM];
__device__ __align__(16) __nv_bfloat16 d_Btl[NQ * GDIM];
__device__ float d_Jb[3 * 11 * NJ];
__device__ __align__(16) __nv_bfloat16 d_gh[NB * GDIM];
__device__ __align__(16) __nv_bfloat16 d_gl[NB * GDIM];
__device__ float d_Rs[NB * NJ * 9];
__device__ float d_Qv[NB * NQ];

// ---------------- helpers ----------------
__device__ __forceinline__ uint32_t smem_u32(const void* p) {
    uint32_t r;
    asm("{ .reg .u64 t; cvta.to.shared.u64 t, %1; cvt.u32.u64 %0, t; }" : "=r"(r) : "l"(p));
    return r;
}
__device__ __forceinline__ void cp_async16(uint32_t saddr, const void* gaddr) {
    asm volatile("cp.async.cg.shared.global [%0], [%1], 16;" :: "r"(saddr), "l"(gaddr) : "memory");
}
__device__ __forceinline__ void cp_commit() {
    asm volatile("cp.async.commit_group;" ::: "memory");
}
__device__ __forceinline__ void ldsm_x4(uint32_t& r0, uint32_t& r1, uint32_t& r2, uint32_t& r3,
                                        uint32_t addr) {
    asm volatile("ldmatrix.sync.aligned.m8n8.x4.shared.b16 {%0,%1,%2,%3}, [%4];"
                 : "=r"(r0), "=r"(r1), "=r"(r2), "=r"(r3) : "r"(addr));
}
// bf16 mma (for gemm3m)
__device__ __forceinline__ void mma16816(float& d0, float& d1, float& d2, float& d3,
                                         uint32_t a0, uint32_t a1, uint32_t a2, uint32_t a3,
                                         uint32_t b0, uint32_t b1) {
    asm volatile("mma.sync.aligned.m16n8k16.row.col.f32.bf16.bf16.f32 "
                 "{%0,%1,%2,%3}, {%4,%5,%6,%7}, {%8,%9}, {%0,%1,%2,%3};"
                 : "+f"(d0), "+f"(d1), "+f"(d2), "+f"(d3)
                 : "r"(a0), "r"(a1), "r"(a2), "r"(a3), "r"(b0), "r"(b1));
}
// fp16 mma (for big GEMM)
__device__ __forceinline__ void mma16816h(float& d0, float& d1, float& d2, float& d3,
                                          uint32_t a0, uint32_t a1, uint32_t a2, uint32_t a3,
                                          uint32_t b0, uint32_t b1) {
    asm volatile("mma.sync.aligned.m16n8k16.row.col.f32.f16.f16.f32 "
                 "{%0,%1,%2,%3}, {%4,%5,%6,%7}, {%8,%9}, {%0,%1,%2,%3};"
                 : "+f"(d0), "+f"(d1), "+f"(d2), "+f"(d3)
                 : "r"(a0), "r"(a1), "r"(a2), "r"(a3), "r"(b0), "r"(b1));
}
// swizzled byte offset in a [rows][32 x 16-bit] tile: row r, 16B chunk c in 0..3
__device__ __forceinline__ uint32_t swz32(int r, int c) {
    return (uint32_t)(r * 64 + ((c ^ ((r >> 1) & 3)) << 4));
}

// pack 4 floats into bf16 hi/lo 8-byte words
union PKB { __nv_bfloat16 b[4]; uint2 u; };
__device__ __forceinline__ void pack_hl(const float* v, uint2& hu, uint2& lu) {
    PKB H, L;
#pragma unroll
    for (int q = 0; q < 4; ++q) {
        __nv_bfloat16 h = __float2bfloat16(v[q]);
        H.b[q] = h;
        L.b[q] = __float2bfloat16(v[q] - __bfloat162float(h));
    }
    hu = H.u; lu = L.u;
}
// pack 4 floats (pre-scaled) into fp16 hi/lo 8-byte words
union PKH { __half b[4]; uint2 u; };
__device__ __forceinline__ void pack_hl_h(const float* v, uint2& hu, uint2& lu) {
    PKH H, L;
#pragma unroll
    for (int q = 0; q < 4; ++q) {
        float s = v[q] * ASCALE;
        __half h = __float2half_rn(s);
        H.b[q] = h;
        L.b[q] = __float2half_rn(s - __half2float(h));
    }
    hu = H.u; lu = L.u;
}
__device__ __forceinline__ uint2 pack_h(const float* v) {
    PKH P;
#pragma unroll
    for (int q = 0; q < 4; ++q) P.b[q] = __float2half_rn(v[q]);
    return P.u;
}

// ---------------- prep: gather A (fp16 hi/lo, scaled) + transpose Jr/w ----------
__global__ void k_prep(const float* __restrict__ posedirs,
                       const float* __restrict__ shapedirs,
                       const float* __restrict__ vtempl,
                       const float* __restrict__ Jr, const float* __restrict__ w,
                       __half* __restrict__ Ah, __half* __restrict__ Al,
                       float* __restrict__ Jrt, float* __restrict__ wt)
{
    const int idx = blockIdx.x * 256 + threadIdx.x;
    const int y = blockIdx.y;
    const int v = idx * 4;
    if (v >= KPAD) return;

    if (y < TROWS) {
        const int t = y;
        float c0[4] = {0,0,0,0}, c1[4] = {0,0,0,0}, c2[4] = {0,0,0,0};
        const float* src = nullptr;
        if (t < NPOSE)           src = posedirs + (size_t)t * (NV*3);
        else if (t < NPOSE + 10) src = shapedirs + (size_t)(t-NPOSE) * (NV*3);
        else if (t == 217)       src = vtempl;

        if (src) {
            if (v + 3 < NV) {
                const float2* s2 = (const float2*)(src + (size_t)v*3);
                float2 f0 = s2[0], f1 = s2[1], f2 = s2[2];
                float2 f3 = s2[3], f4 = s2[4], f5 = s2[5];
                c0[0]=f0.x; c1[0]=f0.y; c2[0]=f1.x;
                c0[1]=f1.y; c1[1]=f2.x; c2[1]=f2.y;
                c0[2]=f3.x; c1[2]=f3.y; c2[2]=f4.x;
                c0[3]=f4.y; c1[3]=f5.x; c2[3]=f5.y;
            } else {
                for (int q = 0; q < 4 && v + q < NV; ++q) {
                    c0[q] = src[(size_t)(v+q)*3 + 0];
                    c1[q] = src[(size_t)(v+q)*3 + 1];
                    c2[q] = src[(size_t)(v+q)*3 + 2];
                }
            }
        } else if (t == 218) {
#pragma unroll
            for (int q = 0; q < 4; ++q) c0[q] = (v + q < NV) ? 1.f : 0.f;
        } else {
            return;   // pad rows stay zero (zero-initialized globals)
        }

        const float* ch[3] = {c0, c1, c2};
#pragma unroll
        for (int c = 0; c < 3; ++c) {
            uint2 hu, lu;
            pack_hl_h(ch[c], hu, lu);
            size_t o = (size_t)(c*TROWS + t) * KPAD + v;
            *(uint2*)(Ah + o) = hu;
            *(uint2*)(Al + o) = lu;
        }
        return;
    }

    const int j = y - TROWS;
    float a[4] = {0,0,0,0}, b[4] = {0,0,0,0};
#pragma unroll
    for (int q = 0; q < 4; ++q) {
        if (v + q < NV) {
            a[q] = Jr[(size_t)(v+q)*24 + j];
            b[q] = w [(size_t)(v+q)*24 + j];
        }
    }
    *(float4*)(Jrt + (size_t)j * KPAD + v) = make_float4(a[0], a[1], a[2], a[3]);
    *(float4*)(wt  + (size_t)j * KPAD + v) = make_float4(b[0], b[1], b[2], b[3]);
}

// ---------------- B[jk][v] = Jr[v,j]*w[v,k] -> single fp16 ----------------
__global__ void k_prepB(const float* __restrict__ Jrt, const float* __restrict__ wt,
                        __half* __restrict__ B)
{
    const int idx = blockIdx.x * 256 + threadIdx.x;
    const int v = idx * 4;
    if (v >= KPAD) return;
    const int jk = blockIdx.y;
    const int j = jk / 24, k = jk - j * 24;

    float4 a = *(const float4*)(Jrt + (size_t)j * KPAD + v);
    float4 b = *(const float4*)(wt  + (size_t)k * KPAD + v);
    float p[4] = {a.x*b.x, a.y*b.y, a.z*b.z, a.w*b.w};
    *(uint2*)(B + (size_t)jk * KPAD + v) = pack_h(p);
}

// ---------------- big projection GEMM (fp16, 2-pass), STG split-K epilogue -----
__global__ __launch_bounds__(256, 3) void k_mma(const __half* __restrict__ Ah,
                                                const __half* __restrict__ Al,
                                                const __half* __restrict__ B,
                                                float* __restrict__ Cpart)
{
    extern __shared__ char sm[];
    const uint32_t sbase = smem_u32(sm);
    const int tid = threadIdx.x;
    const int lane = tid & 31, wid = tid >> 5;
    const int n0 = blockIdx.x * BN;
    const int m0 = blockIdx.y * BM;
    const int kbase = blockIdx.z * (KIT * BK);

    const int wm = wid & 3;
    const int wn = wid >> 2;

    const int lr = tid >> 2, lc = tid & 3;

    auto load_stage = [&](int t) {
        const uint32_t s0 = sbase + (uint32_t)(t % MNST) * MSTG;
        const uint32_t sAh = s0;
        const uint32_t sAl = s0 + AHSZ;
        const uint32_t sB  = s0 + 2*AHSZ;
        const int kk = kbase + t * BK;
        cp_async16(sAh + swz32(lr,      lc), Ah + (size_t)(m0 + lr)      * KPAD + kk + lc*8);
        cp_async16(sAh + swz32(lr + 64, lc), Ah + (size_t)(m0 + lr + 64) * KPAD + kk + lc*8);
        cp_async16(sAl + swz32(lr,      lc), Al + (size_t)(m0 + lr)      * KPAD + kk + lc*8);
        cp_async16(sAl + swz32(lr + 64, lc), Al + (size_t)(m0 + lr + 64) * KPAD + kk + lc*8);
        cp_async16(sB  + swz32(lr, lc),      B  + (size_t)(n0 + lr)      * KPAD + kk + lc*8);
        cp_commit();
    };

    float acc[2][4][4] = {};

    load_stage(0);
    load_stage(1);

    for (int t = 0; t < KIT; ++t) {
        asm volatile("cp.async.wait_group 1;" ::: "memory");
        __syncthreads();
        if (t + 2 < KIT) load_stage(t + 2);

        const uint32_t s0  = sbase + (uint32_t)(t % MNST) * MSTG;
        const uint32_t sAh = s0;
        const uint32_t sAl = s0 + AHSZ;
        const uint32_t sB  = s0 + 2*AHSZ;

#pragma unroll
        for (int ks = 0; ks < 2; ++ks) {
            uint32_t bb[4][2];
#pragma unroll
            for (int j2 = 0; j2 < 2; j2++) {
                int n = wn*32 + j2*16 + (lane & 7) + ((lane >> 4) << 3);
                int c = ks*2 + ((lane >> 3) & 1);
                uint32_t q0, q1, q2, q3;
                ldsm_x4(q0, q1, q2, q3, sB + swz32(n, c));
                bb[j2*2+0][0] = q0; bb[j2*2+0][1] = q1;
                bb[j2*2+1][0] = q2; bb[j2*2+1][1] = q3;
            }
            {
                uint32_t ah[2][4];
#pragma unroll
                for (int i = 0; i < 2; i++) {
                    int r = wm*32 + i*16 + (lane & 15);
                    int c = ks*2 + (lane >> 4);
                    ldsm_x4(ah[i][0], ah[i][1], ah[i][2], ah[i][3], sAh + swz32(r, c));
                }
#pragma unroll
                for (int i = 0; i < 2; i++)
#pragma unroll
                    for (int j = 0; j < 4; j++)
                        mma16816h(acc[i][j][0], acc[i][j][1], acc[i][j][2], acc[i][j][3],
                                  ah[i][0], ah[i][1], ah[i][2], ah[i][3], bb[j][0], bb[j][1]);
            }
            {
                uint32_t al[2][4];
#pragma unroll
                for (int i = 0; i < 2; i++) {
                    int r = wm*32 + i*16 + (lane & 15);
                    int c = ks*2 + (lane >> 4);
                    ldsm_x4(al[i][0], al[i][1], al[i][2], al[i][3], sAl + swz32(r, c));
                }
#pragma unroll
                for (int i = 0; i < 2; i++)
#pragma unroll
                    for (int j = 0; j < 4; j++)
                        mma16816h(acc[i][j][0], acc[i][j][1], acc[i][j][2], acc[i][j][3],
                                  al[i][0], al[i][1], al[i][2], al[i][3], bb[j][0], bb[j][1]);
            }
        }
    }

    // split-K epilogue: plain STG.64; skip all-zero pad rows
    float* cp = Cpart + (size_t)blockIdx.z * ((size_t)MPAD * N2);
#pragma unroll
    for (int i = 0; i < 2; i++) {
        int row = m0 + wm*32 + i*16 + (lane >> 2);
        if (row < M2) {
#pragma unroll
            for (int j = 0; j < 4; j++) {
                int col = n0 + wn*32 + j*8 + (lane & 3)*2;
                *(float2*)(cp + (size_t)row * N2 + col)       = make_float2(acc[i][j][0], acc[i][j][1]);
                *(float2*)(cp + (size_t)(row + 8) * N2 + col) = make_float2(acc[i][j][2], acc[i][j][3]);
            }
        }
    }
}

// ---------------- fused: reduce+unscale+transpose + features + Jb(warp) --------
__global__ void k_mid(const float* __restrict__ Cpart,
                      const float* __restrict__ beta,
                      const float* __restrict__ theta,
                      float* __restrict__ C2,
                      __nv_bfloat16* __restrict__ Bth, __nv_bfloat16* __restrict__ Btl,
                      __nv_bfloat16* __restrict__ gh, __nv_bfloat16* __restrict__ gl,
                      float* __restrict__ Rs, float* __restrict__ Jb)
{
    const int bid = blockIdx.x;
    const int tid = threadIdx.x;

    if (bid < TR2_BLOCKS) {
        __shared__ float s[32][33];
        const int n0 = (bid % 18) * 32;
        const int m0 = (bid / 18) * 32;
        // float4 reduce: thread -> (m = tid>>3, n-chunk of 4 = (tid&7)*4)
        const int m_loc = tid >> 3;
        const int n4 = (tid & 7) * 4;
        float4 sum = make_float4(0.f, 0.f, 0.f, 0.f);
#pragma unroll
        for (int p = 0; p < ZSPL; ++p) {
            float4 v = *(const float4*)(Cpart + (size_t)p * (MPAD*N2)
                                        + (size_t)(m0 + m_loc) * N2 + n0 + n4);
            sum.x += v.x; sum.y += v.y; sum.z += v.z; sum.w += v.w;
        }
        sum.x *= INVSC; sum.y *= INVSC; sum.z *= INVSC; sum.w *= INVSC;
        *(float4*)(C2 + (size_t)(m0 + m_loc) * N2 + n0 + n4) = sum;
        s[m_loc][n4 + 0] = sum.x;
        s[m_loc][n4 + 1] = sum.y;
        s[m_loc][n4 + 2] = sum.z;
        s[m_loc][n4 + 3] = sum.w;
        __syncthreads();
        const int c  = m0 / TROWS;
        const int t0 = m0 - c * TROWS;
        const int n_loc = tid >> 3;
        const int tc = tid & 7;
        float v[4];
#pragma unroll
        for (int q = 0; q < 4; ++q) v[q] = s[tc*4 + q][n_loc];
        uint2 hu, lu;
        pack_hl(v, hu, lu);
        size_t o = (size_t)(c*N2 + n0 + n_loc) * GDIM + t0 + tc*4;
        *(uint2*)(Bth + o) = hu;
        *(uint2*)(Btl + o) = lu;
        return;
    }

    if (bid < TR2_BLOCKS + FEAT_BLOCKS) {
        const int b = (bid - TR2_BLOCKS) * 8 + (tid >> 5);
        const int lane = tid & 31;
        auto wr = [&](int idx, float v) {
            __nv_bfloat16 h = __float2bfloat16(v);
            __nv_bfloat16 l = __float2bfloat16(v - __bfloat162float(h));
            gh[(size_t)b*GDIM + idx] = h;
            gl[(size_t)b*GDIM + idx] = l;
        };
        if (lane < 24) {
            int k = lane;
            float t0 = theta[b*72 + k*3 + 0];
            float t1 = theta[b*72 + k*3 + 1];
            float t2 = theta[b*72 + k*3 + 2];
            float a0 = t0 + 1e-8f, a1 = t1 + 1e-8f, a2 = t2 + 1e-8f;
            float angle = sqrtf(a0*a0 + a1*a1 + a2*a2);
            float inv = 1.f / angle;
            float n0 = t0*inv, n1 = t1*inv, n2 = t2*inv;
            float half = 0.5f * angle;
            float w = cosf(half), s = sinf(half);
            float x = s*n0, y = s*n1, z = s*n2;
            float qn = rsqrtf(w*w + x*x + y*y + z*z);
            w *= qn; x *= qn; y *= qn; z *= qn;
            float rot[9];
            rot[0] = w*w + x*x - y*y - z*z;
            rot[1] = 2.f*(x*y - w*z);
            rot[2] = 2.f*(x*z + w*y);
            rot[3] = 2.f*(x*y + w*z);
            rot[4] = w*w - x*x + y*y - z*z;
            rot[5] = 2.f*(y*z - w*x);
            rot[6] = 2.f*(x*z - w*y);
            rot[7] = 2.f*(y*z + w*x);
            rot[8] = w*w - x*x - y*y + z*z;
            float* rs = Rs + (size_t)(b*24 + k) * 9;
#pragma unroll
            for (int e = 0; e < 9; e++) rs[e] = rot[e];
            if (k > 0) {
#pragma unroll
                for (int e = 0; e < 9; e++)
                    wr((k-1)*9 + e, rot[e] - ((e == 0 || e == 4 || e == 8) ? 1.f : 0.f));
            }
        }
        if (lane < 10)       wr(207 + lane, beta[b*10 + lane]);
        else if (lane == 10) wr(217, 1.f);
        else if (lane < 17)  wr(207 + lane, 0.f);
        return;
    }

    // rest-joint basis: one warp per output, lanes cover the 8x24 element grid
    {
        const int wslot = (bid - TR2_BLOCKS - FEAT_BLOCKS) * 8 + (tid >> 5);
        if (wslot >= JB_OUT) return;
        const int lane = tid & 31;
        int c = wslot / (11*NJ);
        int r = wslot - c * (11*NJ);
        int i = r / NJ;
        int j = r - i * NJ;
        const size_t rowoff = (size_t)(c*TROWS + 207 + i) * N2 + j*24;
        float s = 0.f;
#pragma unroll
        for (int e = lane; e < 192; e += 32) {      // 6 iterations
            int p = e / 24, k = e - (e / 24) * 24;
            s += Cpart[(size_t)p * (MPAD*N2) + rowoff + k];
        }
#pragma unroll
        for (int off = 16; off > 0; off >>= 1)
            s += __shfl_xor_sync(0xffffffffu, s, off);
        if (lane == 0) Jb[wslot] = s * INVSC;
    }
}

// ---------------- per-batch GEMM Qv = g @ C2t^T (bf16 mma, 3-pass) --------------
__global__ __launch_bounds__(128) void k_gemm3m(const __nv_bfloat16* __restrict__ gh,
                                                const __nv_bfloat16* __restrict__ gl,
                                                const __nv_bfloat16* __restrict__ Bth,
                                                const __nv_bfloat16* __restrict__ Btl,
                                                float* __restrict__ Qv)
{
    extern __shared__ char sm[];
    const uint32_t sbase = smem_u32(sm);
    const int tid = threadIdx.x;
    const int lane = tid & 31, wid = tid >> 5;
    const int n0 = blockIdx.x * 64;
    const int m0 = blockIdx.y * 64;

    const int lr0 = tid >> 2, lc0 = tid & 3;
    const int lr1 = lr0 + 32;

    auto load_stage = [&](int t) {
        const int seg = t / 7;
        const int kk = (t - seg*7) * BK;
        const __nv_bfloat16* Aptr = (seg == 2) ? gl : gh;
        const __nv_bfloat16* Bptr = (seg == 1) ? Btl : Bth;
        const uint32_t sa = sbase + (uint32_t)(t & 3) * S2STG;
        const uint32_t sb = sa + S2ASZ;
        cp_async16(sa + swz32(lr0, lc0), Aptr + (size_t)(m0 + lr0) * GDIM + kk + lc0*8);
        cp_async16(sa + swz32(lr1, lc0), Aptr + (size_t)(m0 + lr1) * GDIM + kk + lc0*8);
        cp_async16(sb + swz32(lr0, lc0), Bptr + (size_t)(n0 + lr0) * GDIM + kk + lc0*8);
        cp_async16(sb + swz32(lr1, lc0), Bptr + (size_t)(n0 + lr1) * GDIM + kk + lc0*8);
        cp_commit();
    };

    float acc[8][4] = {};

    load_stage(0);
    load_stage(1);
    load_stage(2);

    for (int t = 0; t < G3ITER; ++t) {
        asm volatile("cp.async.wait_group 2;" ::: "memory");
        __syncthreads();
        if (t + 3 < G3ITER) load_stage(t + 3);

        const uint32_t sa = sbase + (uint32_t)(t & 3) * S2STG;
        const uint32_t sb = sa + S2ASZ;
#pragma unroll
        for (int ks = 0; ks < 2; ++ks) {
            uint32_t a[4];
            {
                int r = wid*16 + (lane & 15);
                int c = ks*2 + (lane >> 4);
                ldsm_x4(a[0], a[1], a[2], a[3], sa + swz32(r, c));
            }
            uint32_t bfr[8][2];
#pragma unroll
            for (int j2 = 0; j2 < 4; j2++) {
                int n = j2*16 + (lane & 7) + ((lane >> 4) << 3);
                int c = ks*2 + ((lane >> 3) & 1);
                uint32_t q0, q1, q2, q3;
                ldsm_x4(q0, q1, q2, q3, sb + swz32(n, c));
                bfr[j2*2+0][0] = q0; bfr[j2*2+0][1] = q1;
                bfr[j2*2+1][0] = q2; bfr[j2*2+1][1] = q3;
            }
#pragma unroll
            for (int j = 0; j < 8; j++)
                mma16816(acc[j][0], acc[j][1], acc[j][2], acc[j][3],
                         a[0], a[1], a[2], a[3], bfr[j][0], bfr[j][1]);
        }
    }

    {
        int row = m0 + wid*16 + (lane >> 2);
#pragma unroll
        for (int j = 0; j < 8; j++) {
            int col = n0 + j*8 + (lane & 3)*2;
            *(float2*)(Qv + (size_t)row * NQ + col)       = make_float2(acc[j][0], acc[j][1]);
            *(float2*)(Qv + (size_t)(row + 8) * NQ + col) = make_float2(acc[j][2], acc[j][3]);
        }
    }
}

// ---------------- kinematic chain + combine ----------------
__global__ __launch_bounds__(128) void k_final(const float* __restrict__ beta,
                                               const float* __restrict__ Rs,
                                               const float* __restrict__ Jb,
                                               const float* __restrict__ C2,
                                               const float* __restrict__ Qv,
                                               float* __restrict__ out)
{
    __shared__ float sR[216];
    __shared__ float sJ[72];
    __shared__ float sG[288];
    __shared__ float sAt[72];
    __shared__ float sBeta[10];
    const int b = blockIdx.x;
    const int tid = threadIdx.x;

    for (int i = tid; i < 216; i += 128) sR[i] = Rs[(size_t)b*216 + i];
    if (tid < 10) sBeta[tid] = beta[b*10 + tid];
    __syncthreads();

    if (tid < 72) {
        int j = tid / 3, c = tid - j*3;
        float v = Jb[(c*11 + 10)*NJ + j];
#pragma unroll
        for (int i = 0; i < 10; i++) v = fmaf(sBeta[i], Jb[(c*11 + i)*NJ + j], v);
        sJ[j*3 + c] = v;
    }
    __syncthreads();

    if (tid < 12) {
        int r = tid >> 2, cc = tid & 3;
        sG[tid] = (cc < 3) ? sR[r*3 + cc] : sJ[r];
        __syncwarp(0x0fff);
        for (int i = 1; i < 24; i++) {
            int p = c_parents[i];
            float v;
            if (cc < 3) {
                v = sG[p*12 + r*4 + 0] * sR[i*9 + 0 + cc]
                  + sG[p*12 + r*4 + 1] * sR[i*9 + 3 + cc]
                  + sG[p*12 + r*4 + 2] * sR[i*9 + 6 + cc];
            } else {
                float tx = sJ[i*3+0] - sJ[p*3+0];
                float ty = sJ[i*3+1] - sJ[p*3+1];
                float tz = sJ[i*3+2] - sJ[p*3+2];
                v = sG[p*12 + r*4 + 0] * tx
                  + sG[p*12 + r*4 + 1] * ty
                  + sG[p*12 + r*4 + 2] * tz
                  + sG[p*12 + r*4 + 3];
            }
            sG[i*12 + r*4 + cc] = v;
            __syncwarp(0x0fff);
        }
    }
    __syncthreads();

    if (tid < 72) {
        int k = tid / 3, c = tid - k*3;
        sAt[k*3 + c] = sG[k*12 + c*4 + 3]
                     - (sG[k*12 + c*4 + 0] * sJ[k*3 + 0]
                      + sG[k*12 + c*4 + 1] * sJ[k*3 + 1]
                      + sG[k*12 + c*4 + 2] * sJ[k*3 + 2]);
    }
    __syncthreads();

    if (tid < 72) {
        int j = tid / 3, c = tid - j*3;
        const float* qb = Qv + (size_t)b * NQ;
        const float* s0 = C2 + 218 * N2;
        float acc = 0.f;
#pragma unroll
        for (int k = 0; k < 24; k++) {
            int jk = j*24 + k;
            acc = fmaf(sG[k*12 + c*4 + 0], qb[jk],        acc);
            acc = fmaf(sG[k*12 + c*4 + 1], qb[576 + jk],  acc);
            acc = fmaf(sG[k*12 + c*4 + 2], qb[1152 + jk], acc);
            acc = fmaf(sAt[k*3 + c],       s0[jk],        acc);
        }
        out[b*72 + j*3 + c] = acc;
    }
}

// ---------------- launcher ----------------
extern "C" void kernel_launch(void* const* d_in, const int* in_sizes, int n_in,
                              void* d_out, int out_size)
{
    const float* beta      = (const float*)d_in[0];
    const float* theta     = (const float*)d_in[1];
    const float* vtempl    = (const float*)d_in[2];
    const float* shapedirs = (const float*)d_in[3];
    const float* posedirs  = (const float*)d_in[4];
    const float* Jr        = (const float*)d_in[5];
    const float* wts       = (const float*)d_in[6];
    float* out = (float*)d_out;

    __half *Ah, *Al, *B;
    __nv_bfloat16 *Bth, *Btl, *gh, *gl;
    float *Jrt, *wt, *Cpart, *C2, *Jb, *Rs, *Qv;
    cudaGetSymbolAddress((void**)&Ah, d_Ah);
    cudaGetSymbolAddress((void**)&Al, d_Al);
    cudaGetSymbolAddress((void**)&B,  d_B);
    cudaGetSymbolAddress((void**)&Bth, d_Bth);
    cudaGetSymbolAddress((void**)&Btl, d_Btl);
    cudaGetSymbolAddress((void**)&gh, d_gh);
    cudaGetSymbolAddress((void**)&gl, d_gl);
    cudaGetSymbolAddress((void**)&Jrt, d_Jrt);
    cudaGetSymbolAddress((void**)&wt, d_wt);
    cudaGetSymbolAddress((void**)&Cpart, d_Cpart);
    cudaGetSymbolAddress((void**)&C2, d_C2);
    cudaGetSymbolAddress((void**)&Jb, d_Jb);
    cudaGetSymbolAddress((void**)&Rs, d_Rs);
    cudaGetSymbolAddress((void**)&Qv, d_Qv);

    cudaFuncSetAttribute(k_mma,    cudaFuncAttributeMaxDynamicSharedMemorySize, MSMEM);
    cudaFuncSetAttribute(k_gemm3m, cudaFuncAttributeMaxDynamicSharedMemorySize, S2SMEM);

    k_prep<<<dim3(7, TROWS + NJ), 256>>>(posedirs, shapedirs, vtempl, Jr, wts,
                                         Ah, Al, Jrt, wt);
    k_prepB<<<dim3(7, N2), 256>>>(Jrt, wt, B);
    k_mma<<<dim3(N2/BN, MPAD/BM, ZSPL), 256, MSMEM>>>(Ah, Al, B, Cpart);
    k_mid<<<TR2_BLOCKS + FEAT_BLOCKS + JB_BLOCKS, 256>>>(Cpart, beta, theta, C2,
                                                         Bth, Btl, gh, gl, Rs, Jb);
    k_gemm3m<<<dim3(NQ/64, NB/64), 128, S2SMEM>>>(gh, gl, Bth, Btl, Qv);
    k_final<<<NB, 128>>>(beta, Rs, Jb, C2, Qv, out);
}